// round 15
// baseline (speedup 1.0000x reference)
#include <cuda_runtime.h>
#include <cuda_fp16.h>

#define NN 100000
#define NE 1600000
#define NG 512
#define F_IN 128
#define F_H1 128
#define F_H2 256
#define N_GROUPS 16
#define N_FAM 10

#define SCAN_BLK 256
#define NBLK_SCAN ((NN + SCAN_BLK - 1) / SCAN_BLK)   // 391

// ---------------- scratch (device globals: allocation-guard-safe) ----------------
__device__ __half g_xw1s[(size_t)NN * F_H1]; // dinv * (x @ W1), fp16 (25.6 MB, L2-resident)
__device__ __half g_h1s[(size_t)NN * F_H1];  // dinv * relu(agg1), fp16 (25.6 MB, L2-resident)
__device__ __half g_w1t[F_H1 * F_IN];        // W1 transposed [n][k], fp16
__device__ float g_dinv[NN];                 // rsqrt(deg+1)
__device__ int   g_deg[NN];                  // in-degree histogram
__device__ int   g_rowptr[NN + 1];           // CSR row pointers (by dst)
__device__ int   g_fill[NN];                 // running fill cursors
__device__ int   g_blocksum[NBLK_SCAN + 1];  // scan partials
__device__ int   g_csr_src[NE];              // src ids, dst-ordered
__device__ float g_pool[NG * F_H1];          // pooled sums [512,128] (fp32)
__device__ float g_cnt[NG];                  // segment counts

__device__ __forceinline__ unsigned smem_u32(const void* p) {
    unsigned a;
    asm("{.reg .u64 t; cvta.to.shared.u64 t, %1; cvt.u32.u64 %0, t;}" : "=r"(a) : "l"(p));
    return a;
}

// ---------------- zero + degree histogram ----------------
// NOTE: must cover NN threads (g_deg) — replay idempotence.
__global__ void zero_kernel() {
    int i = blockIdx.x * blockDim.x + threadIdx.x;
    if (i < NN) g_deg[i] = 0;
    if (i < NG * F_H1) g_pool[i] = 0.f;
    if (i < NG) g_cnt[i] = 0.f;
}

// 4 edges per thread, int4 loads (NE % 4 == 0)
__global__ void hist_kernel(const int* __restrict__ dst) {
    int i = blockIdx.x * blockDim.x + threadIdx.x;
    if (i >= NE / 4) return;
    int4 d = ((const int4*)dst)[i];
    atomicAdd(&g_deg[d.x], 1);
    atomicAdd(&g_deg[d.y], 1);
    atomicAdd(&g_deg[d.z], 1);
    atomicAdd(&g_deg[d.w], 1);
}

// ---------------- exclusive scan of g_deg -> g_rowptr (dinv fused in) ----------------
__global__ void scan_block_kernel() {
    __shared__ int s[SCAN_BLK];
    int tid = threadIdx.x;
    int i = blockIdx.x * SCAN_BLK + tid;
    int v = (i < NN) ? g_deg[i] : 0;
    if (i < NN) g_dinv[i] = rsqrtf((float)v + 1.0f);   // fused dinv
    s[tid] = v;
    __syncthreads();
#pragma unroll
    for (int off = 1; off < SCAN_BLK; off <<= 1) {
        int t = (tid >= off) ? s[tid - off] : 0;
        __syncthreads();
        s[tid] += t;
        __syncthreads();
    }
    if (i < NN) g_rowptr[i] = s[tid] - v;      // exclusive within block
    if (tid == SCAN_BLK - 1) g_blocksum[blockIdx.x] = s[tid];
}

__global__ void scan_sums_kernel() {
    __shared__ int s[512];
    int tid = threadIdx.x;                      // 512 threads
    int v = (tid < NBLK_SCAN) ? g_blocksum[tid] : 0;
    s[tid] = v;
    __syncthreads();
#pragma unroll
    for (int off = 1; off < 512; off <<= 1) {
        int t = (tid >= off) ? s[tid - off] : 0;
        __syncthreads();
        s[tid] += t;
        __syncthreads();
    }
    if (tid < NBLK_SCAN) g_blocksum[tid] = s[tid] - v;   // exclusive
}

__global__ void scan_add_kernel() {
    int i = blockIdx.x * blockDim.x + threadIdx.x;
    if (i < NN) {
        int r = g_rowptr[i] + g_blocksum[i / SCAN_BLK];
        g_rowptr[i] = r;
        g_fill[i] = r;
    }
    if (i == 0) g_rowptr[NN] = NE;
}

// ---------------- CSR fill (src ids only), 4 edges per thread ----------------
__global__ void csr_fill_kernel(const int* __restrict__ src, const int* __restrict__ dst) {
    int i = blockIdx.x * blockDim.x + threadIdx.x;
    if (i >= NE / 4) return;
    int4 s4 = ((const int4*)src)[i];
    int4 d4 = ((const int4*)dst)[i];
    g_csr_src[atomicAdd(&g_fill[d4.x], 1)] = s4.x;
    g_csr_src[atomicAdd(&g_fill[d4.y], 1)] = s4.y;
    g_csr_src[atomicAdd(&g_fill[d4.z], 1)] = s4.z;
    g_csr_src[atomicAdd(&g_fill[d4.w], 1)] = s4.w;
}

// ---------------- W1 transpose + fp16 convert: W1T[n][k] = W1[k][n] ----------------
__global__ void w1t_kernel(const float* __restrict__ W1) {
    int i = blockIdx.x * blockDim.x + threadIdx.x;   // 16384
    int n = i >> 7, k = i & 127;
    g_w1t[n * 128 + k] = __float2half(W1[k * 128 + n]);
}

// ---------------- GEMM1 (tensor cores): xw1s = fp16(dinv * (x @ W1)) ----------------
#define AS_STRIDE 136   // halves; 272B row stride -> conflict-free ldmatrix
__global__ __launch_bounds__(512) void gemm1_mma_kernel(const float* __restrict__ A,
                                                        __half* __restrict__ C, int M) {
    extern __shared__ char smem_raw[];
    __half* As = (__half*)smem_raw;                      // [128][AS_STRIDE]
    __half* Bs = As + 128 * AS_STRIDE;                   // [128][AS_STRIDE] (n-major)
    int tid = threadIdx.x;
    int bm = blockIdx.x * 128;

    for (int idx = tid; idx < 128 * 32; idx += 512) {
        int m = idx >> 5, q = idx & 31;
        int gm = bm + m;
        float4 v = (gm < M) ? ((const float4*)(A + (size_t)gm * 128))[q]
                            : make_float4(0.f, 0.f, 0.f, 0.f);
        __half2 h0 = __floats2half2_rn(v.x, v.y);
        __half2 h1 = __floats2half2_rn(v.z, v.w);
        *(__half2*)&As[m * AS_STRIDE + q * 4]     = h0;
        *(__half2*)&As[m * AS_STRIDE + q * 4 + 2] = h1;
    }
    for (int idx = tid; idx < 2048; idx += 512) {
        int n = idx >> 4, q = idx & 15;
        *(uint4*)&Bs[n * AS_STRIDE + q * 8] = ((const uint4*)(g_w1t + n * 128))[q];
    }
    __syncthreads();

    int lane = tid & 31, warp = tid >> 5;
    int wm = (warp >> 2) * 32;
    int wn = (warp & 3) * 32;
    float acc[2][4][4];
#pragma unroll
    for (int i = 0; i < 2; i++)
#pragma unroll
        for (int j = 0; j < 4; j++)
#pragma unroll
            for (int r = 0; r < 4; r++) acc[i][j][r] = 0.f;

    int lr = (lane & 7) + ((lane >> 3) & 1) * 8;
    int lk = ((lane >> 4) & 1) * 8;
    int l16 = lane & 15;
    int brow = l16 & 7;
    int bk = ((l16 >> 3) & 1) * 8;

#pragma unroll
    for (int k0 = 0; k0 < 128; k0 += 16) {
        unsigned a[2][4];
#pragma unroll
        for (int fi = 0; fi < 2; fi++) {
            unsigned addr = smem_u32(&As[(wm + fi * 16 + lr) * AS_STRIDE + k0 + lk]);
            asm volatile("ldmatrix.sync.aligned.m8n8.x4.shared.b16 {%0,%1,%2,%3}, [%4];"
                         : "=r"(a[fi][0]), "=r"(a[fi][1]), "=r"(a[fi][2]), "=r"(a[fi][3])
                         : "r"(addr));
        }
        unsigned b[4][2];
#pragma unroll
        for (int fj = 0; fj < 4; fj++) {
            unsigned addr = smem_u32(&Bs[(wn + fj * 8 + brow) * AS_STRIDE + k0 + bk]);
            asm volatile("ldmatrix.sync.aligned.m8n8.x2.shared.b16 {%0,%1}, [%2];"
                         : "=r"(b[fj][0]), "=r"(b[fj][1])
                         : "r"(addr));
        }
#pragma unroll
        for (int fi = 0; fi < 2; fi++)
#pragma unroll
            for (int fj = 0; fj < 4; fj++) {
                asm volatile(
                    "mma.sync.aligned.m16n8k16.row.col.f32.f16.f16.f32 "
                    "{%0,%1,%2,%3}, {%4,%5,%6,%7}, {%8,%9}, {%0,%1,%2,%3};"
                    : "+f"(acc[fi][fj][0]), "+f"(acc[fi][fj][1]),
                      "+f"(acc[fi][fj][2]), "+f"(acc[fi][fj][3])
                    : "r"(a[fi][0]), "r"(a[fi][1]), "r"(a[fi][2]), "r"(a[fi][3]),
                      "r"(b[fj][0]), "r"(b[fj][1]));
            }
    }

#pragma unroll
    for (int fi = 0; fi < 2; fi++) {
        int r0 = bm + wm + fi * 16 + (lane >> 2);
        int r1 = r0 + 8;
        float d0 = (r0 < M) ? g_dinv[r0] : 0.f;
        float d1 = (r1 < M) ? g_dinv[r1] : 0.f;
#pragma unroll
        for (int fj = 0; fj < 4; fj++) {
            int c = wn + fj * 8 + (lane & 3) * 2;
            if (r0 < M)
                *(__half2*)(C + (size_t)r0 * 128 + c) =
                    __floats2half2_rn(acc[fi][fj][0] * d0, acc[fi][fj][1] * d0);
            if (r1 < M)
                *(__half2*)(C + (size_t)r1 * 128 + c) =
                    __floats2half2_rn(acc[fi][fj][2] * d1, acc[fi][fj][3] * d1);
        }
    }
}

// ---------------- layer-1 gather: 2 nodes/warp, LDG.128, prescaled fp16 rows ----------------
// h1s[n] = fp16(dinv[n]*relu(dinv[n]*(sum xw1s[s] + xw1s[n]) + b1))
// lanes 0-15 -> node 2w, lanes 16-31 -> node 2w+1; lane q loads uint4 (8 halves).
__global__ void gather1_kernel(const float* __restrict__ b1) {
    int w = (blockIdx.x * blockDim.x + threadIdx.x) >> 5;
    int lane = threadIdx.x & 31;
    int n = 2 * w + (lane >> 4);
    if (n >= NN) return;
    int q = lane & 15;
    int e = g_rowptr[n], end = g_rowptr[n + 1];
    float acc[8];
#pragma unroll
    for (int i = 0; i < 8; i++) acc[i] = 0.f;

    for (; e < end; e++) {
        int s = g_csr_src[e];                                   // uniform per half-warp
        uint4 u = ((const uint4*)(g_xw1s + (size_t)s * F_H1))[q];
        float2 p;
        p = __half22float2(*(__half2*)&u.x); acc[0] += p.x; acc[1] += p.y;
        p = __half22float2(*(__half2*)&u.y); acc[2] += p.x; acc[3] += p.y;
        p = __half22float2(*(__half2*)&u.z); acc[4] += p.x; acc[5] += p.y;
        p = __half22float2(*(__half2*)&u.w); acc[6] += p.x; acc[7] += p.y;
    }

    float d = g_dinv[n];
    uint4 us = ((const uint4*)(g_xw1s + (size_t)n * F_H1))[q];
    float sv[8];
    {
        float2 p;
        p = __half22float2(*(__half2*)&us.x); sv[0] = p.x; sv[1] = p.y;
        p = __half22float2(*(__half2*)&us.y); sv[2] = p.x; sv[3] = p.y;
        p = __half22float2(*(__half2*)&us.z); sv[4] = p.x; sv[5] = p.y;
        p = __half22float2(*(__half2*)&us.w); sv[6] = p.x; sv[7] = p.y;
    }
    float4 bb0 = ((const float4*)b1)[q * 2];
    float4 bb1 = ((const float4*)b1)[q * 2 + 1];
    float bv[8] = {bb0.x, bb0.y, bb0.z, bb0.w, bb1.x, bb1.y, bb1.z, bb1.w};
    __half2 hh[4];
#pragma unroll
    for (int i = 0; i < 4; i++) {
        float o0 = d * fmaxf(fmaf(acc[2 * i]     + sv[2 * i],     d, bv[2 * i]),     0.f);
        float o1 = d * fmaxf(fmaf(acc[2 * i + 1] + sv[2 * i + 1], d, bv[2 * i + 1]), 0.f);
        hh[i] = __floats2half2_rn(o0, o1);
    }
    ((uint4*)(g_h1s + (size_t)n * F_H1))[q] = *(uint4*)hh;
}

// ---------------- layer-2 gather + fused pooling: 2 nodes/warp, LDG.128 ----------------
__global__ void gather2_pool_kernel(const int* __restrict__ batch) {
    int w = (blockIdx.x * blockDim.x + threadIdx.x) >> 5;
    int lane = threadIdx.x & 31;
    int n = 2 * w + (lane >> 4);
    if (n >= NN) return;
    int q = lane & 15;
    int e = g_rowptr[n], end = g_rowptr[n + 1];
    float acc[8];
#pragma unroll
    for (int i = 0; i < 8; i++) acc[i] = 0.f;

    for (; e < end; e++) {
        int s = g_csr_src[e];
        uint4 u = ((const uint4*)(g_h1s + (size_t)s * F_H1))[q];
        float2 p;
        p = __half22float2(*(__half2*)&u.x); acc[0] += p.x; acc[1] += p.y;
        p = __half22float2(*(__half2*)&u.y); acc[2] += p.x; acc[3] += p.y;
        p = __half22float2(*(__half2*)&u.z); acc[4] += p.x; acc[5] += p.y;
        p = __half22float2(*(__half2*)&u.w); acc[6] += p.x; acc[7] += p.y;
    }

    float d = g_dinv[n];
    uint4 us = ((const uint4*)(g_h1s + (size_t)n * F_H1))[q];
    float sv[8];
    {
        float2 p;
        p = __half22float2(*(__half2*)&us.x); sv[0] = p.x; sv[1] = p.y;
        p = __half22float2(*(__half2*)&us.y); sv[2] = p.x; sv[3] = p.y;
        p = __half22float2(*(__half2*)&us.z); sv[4] = p.x; sv[5] = p.y;
        p = __half22float2(*(__half2*)&us.w); sv[6] = p.x; sv[7] = p.y;
    }
    int g = batch[n];
    float* p = g_pool + (size_t)g * F_H1 + q * 8;
#pragma unroll
    for (int i = 0; i < 8; i++)
        atomicAdd(p + i, (acc[i] + sv[i]) * d);
    if (q == 0) atomicAdd(&g_cnt[g], 1.0f);
}

// ---------------- heads: tiny @W2+b2 per graph, then group + family logits ----------------
__global__ void logits_kernel(const float* __restrict__ W2, const float* __restrict__ b2,
                              const float* __restrict__ Wg, const float* __restrict__ bg,
                              const float* __restrict__ Wf, const float* __restrict__ bf,
                              float* __restrict__ out) {
    __shared__ float p[F_H1];    // pooled mean, [128]
    __shared__ float h2[F_H2];   // pooled @ W2 + b2, [256]
    int b = blockIdx.x;          // graph
    int t = threadIdx.x;         // 256 threads
    float cnt = fmaxf(g_cnt[b], 1.0f);
    if (t < F_H1) p[t] = g_pool[b * F_H1 + t] / cnt;
    __syncthreads();

    {
        float s = b2[t];
#pragma unroll 8
        for (int k = 0; k < F_H1; k++) s = fmaf(p[k], W2[k * F_H2 + t], s);
        h2[t] = s;
    }
    __syncthreads();

    if (t < N_GROUPS) {
        float s = bg[t];
#pragma unroll 8
        for (int k = 0; k < F_H2; k++) s = fmaf(h2[k], Wg[k * N_GROUPS + t], s);
        out[b * N_GROUPS + t] = s;
    }
    if (t < N_GROUPS * N_FAM) {
        int g = t / N_FAM, f = t - g * N_FAM;
        float s = bf[g * N_FAM + f];
        const float* w = Wf + (size_t)g * F_H2 * N_FAM + f;
#pragma unroll 8
        for (int k = 0; k < F_H2; k++) s = fmaf(h2[k], w[k * N_FAM], s);
        out[NG * N_GROUPS + (size_t)g * NG * N_FAM + b * N_FAM + f] = s;
    }
}

// ---------------- launcher: dinv-gated stream overlap (R14 structure) ----------------
extern "C" void kernel_launch(void* const* d_in, const int* in_sizes, int n_in,
                              void* d_out, int out_size) {
    const float* x     = (const float*)d_in[0];
    const int*   ei    = (const int*)d_in[1];     // [2, NE] int32
    const int*   batch = (const int*)d_in[2];
    const float* W1    = (const float*)d_in[3];
    const float* b1    = (const float*)d_in[4];
    const float* W2    = (const float*)d_in[5];
    const float* b2    = (const float*)d_in[6];
    const float* Wg    = (const float*)d_in[7];
    const float* bg    = (const float*)d_in[8];
    const float* Wf    = (const float*)d_in[9];
    const float* bf    = (const float*)d_in[10];
    float* out = (float*)d_out;

    const int* src = ei;
    const int* dst = ei + NE;

    __half* xw1s;
    cudaGetSymbolAddress((void**)&xw1s, g_xw1s);

    const int GEMM_SMEM = 2 * 128 * AS_STRIDE * 2;   // 69632 B
    cudaFuncSetAttribute(gemm1_mma_kernel, cudaFuncAttributeMaxDynamicSharedMemorySize,
                         GEMM_SMEM);

    cudaStream_t s2;
    cudaStreamCreateWithFlags(&s2, cudaStreamNonBlocking);
    cudaEvent_t evFork, evDinv, evGemm;
    cudaEventCreateWithFlags(&evFork, cudaEventDisableTiming);
    cudaEventCreateWithFlags(&evDinv, cudaEventDisableTiming);
    cudaEventCreateWithFlags(&evGemm, cudaEventDisableTiming);

    // fork: w1t has no dependencies — runs immediately on s2
    cudaEventRecord(evFork, 0);
    cudaStreamWaitEvent(s2, evFork, 0);
    w1t_kernel<<<(F_H1 * F_IN + 255) / 256, 256, 0, s2>>>(W1);

    // main stream: histogram chain up to dinv availability
    zero_kernel<<<(NN + 255) / 256, 256>>>();
    hist_kernel<<<(NE / 4 + 255) / 256, 256>>>(dst);
    scan_block_kernel<<<NBLK_SCAN, SCAN_BLK>>>();      // produces dinv
    cudaEventRecord(evDinv, 0);

    // s2: gemm1 (needs dinv for its prescale epilogue) overlaps rest of CSR chain
    cudaStreamWaitEvent(s2, evDinv, 0);
    gemm1_mma_kernel<<<(NN + 127) / 128, 512, GEMM_SMEM, s2>>>(x, xw1s, NN);
    cudaEventRecord(evGemm, s2);

    // main stream: finish CSR build concurrently with gemm1
    scan_sums_kernel<<<1, 512>>>();
    scan_add_kernel<<<(NN + 255) / 256, 256>>>();
    csr_fill_kernel<<<(NE / 4 + 255) / 256, 256>>>(src, dst);

    // join: gathers need CSR + xw1s
    cudaStreamWaitEvent(0, evGemm, 0);
    gather1_kernel<<<((NN / 2) * 32 + 255) / 256, 256>>>(b1);
    gather2_pool_kernel<<<((NN / 2) * 32 + 255) / 256, 256>>>(batch);

    // heads: per-graph @W2+b2 then logits
    logits_kernel<<<NG, F_H2>>>(W2, b2, Wg, bg, Wf, bf, out);

    cudaEventDestroy(evFork);
    cudaEventDestroy(evDinv);
    cudaEventDestroy(evGemm);
    cudaStreamDestroy(s2);
}

// round 16
// speedup vs baseline: 1.1692x; 1.1692x over previous
#include <cuda_runtime.h>
#include <cuda_fp16.h>

#define NN 100000
#define NE 1600000
#define NG 512
#define F_IN 128
#define F_H1 128
#define F_H2 256
#define N_GROUPS 16
#define N_FAM 10

#define SCAN_BLK 256
#define NBLK_SCAN ((NN + SCAN_BLK - 1) / SCAN_BLK)   // 391

// ---------------- scratch (device globals: allocation-guard-safe) ----------------
__device__ __half g_xw1s[(size_t)NN * F_H1]; // dinv * (x @ W1), fp16 (25.6 MB, L2-resident)
__device__ __half g_h1s[(size_t)NN * F_H1];  // dinv * relu(agg1), fp16 (25.6 MB, L2-resident)
__device__ __half g_w1t[F_H1 * F_IN];        // W1 transposed [n][k], fp16
__device__ float g_dinv[NN];                 // rsqrt(deg+1)
__device__ int   g_deg[NN];                  // in-degree histogram
__device__ int   g_rowptr[NN + 1];           // CSR row pointers (by dst)
__device__ int   g_fill[NN];                 // running fill cursors
__device__ int   g_blocksum[NBLK_SCAN + 1];  // scan partials
__device__ int   g_csr_src[NE];              // src ids, dst-ordered
__device__ float g_pool[NG * F_H1];          // pooled sums [512,128] (fp32)
__device__ float g_cnt[NG];                  // segment counts

__device__ __forceinline__ unsigned smem_u32(const void* p) {
    unsigned a;
    asm("{.reg .u64 t; cvta.to.shared.u64 t, %1; cvt.u32.u64 %0, t;}" : "=r"(a) : "l"(p));
    return a;
}

// ---------------- zero + degree histogram ----------------
// NOTE: must cover NN threads (g_deg) — replay idempotence.
__global__ void zero_kernel() {
    int i = blockIdx.x * blockDim.x + threadIdx.x;
    if (i < NN) g_deg[i] = 0;
    if (i < NG * F_H1) g_pool[i] = 0.f;
    if (i < NG) g_cnt[i] = 0.f;
}

__global__ void hist_kernel(const int* __restrict__ dst) {
    int e = blockIdx.x * blockDim.x + threadIdx.x;
    if (e < NE) atomicAdd(&g_deg[dst[e]], 1);
}

// ---------------- exclusive scan of g_deg -> g_rowptr (dinv fused in) ----------------
__global__ void scan_block_kernel() {
    __shared__ int s[SCAN_BLK];
    int tid = threadIdx.x;
    int i = blockIdx.x * SCAN_BLK + tid;
    int v = (i < NN) ? g_deg[i] : 0;
    if (i < NN) g_dinv[i] = rsqrtf((float)v + 1.0f);   // fused dinv
    s[tid] = v;
    __syncthreads();
#pragma unroll
    for (int off = 1; off < SCAN_BLK; off <<= 1) {
        int t = (tid >= off) ? s[tid - off] : 0;
        __syncthreads();
        s[tid] += t;
        __syncthreads();
    }
    if (i < NN) g_rowptr[i] = s[tid] - v;      // exclusive within block
    if (tid == SCAN_BLK - 1) g_blocksum[blockIdx.x] = s[tid];
}

__global__ void scan_sums_kernel() {
    __shared__ int s[512];
    int tid = threadIdx.x;                      // 512 threads
    int v = (tid < NBLK_SCAN) ? g_blocksum[tid] : 0;
    s[tid] = v;
    __syncthreads();
#pragma unroll
    for (int off = 1; off < 512; off <<= 1) {
        int t = (tid >= off) ? s[tid - off] : 0;
        __syncthreads();
        s[tid] += t;
        __syncthreads();
    }
    if (tid < NBLK_SCAN) g_blocksum[tid] = s[tid] - v;   // exclusive
}

__global__ void scan_add_kernel() {
    int i = blockIdx.x * blockDim.x + threadIdx.x;
    if (i < NN) {
        int r = g_rowptr[i] + g_blocksum[i / SCAN_BLK];
        g_rowptr[i] = r;
        g_fill[i] = r;
    }
    if (i == 0) g_rowptr[NN] = NE;
}

// ---------------- CSR fill (src ids only) ----------------
__global__ void csr_fill_kernel(const int* __restrict__ src, const int* __restrict__ dst) {
    int e = blockIdx.x * blockDim.x + threadIdx.x;
    if (e >= NE) return;
    int pos = atomicAdd(&g_fill[dst[e]], 1);
    g_csr_src[pos] = src[e];
}

// ---------------- W1 transpose + fp16 convert: W1T[n][k] = W1[k][n] ----------------
__global__ void w1t_kernel(const float* __restrict__ W1) {
    int i = blockIdx.x * blockDim.x + threadIdx.x;   // 16384
    int n = i >> 7, k = i & 127;
    g_w1t[n * 128 + k] = __float2half(W1[k * 128 + n]);
}

// ---------------- GEMM1 (tensor cores): xw1s = fp16(dinv * (x @ W1)) ----------------
#define AS_STRIDE 136   // halves; 272B row stride -> conflict-free ldmatrix
__global__ __launch_bounds__(512) void gemm1_mma_kernel(const float* __restrict__ A,
                                                        __half* __restrict__ C, int M) {
    extern __shared__ char smem_raw[];
    __half* As = (__half*)smem_raw;                      // [128][AS_STRIDE]
    __half* Bs = As + 128 * AS_STRIDE;                   // [128][AS_STRIDE] (n-major)
    int tid = threadIdx.x;
    int bm = blockIdx.x * 128;

    for (int idx = tid; idx < 128 * 32; idx += 512) {
        int m = idx >> 5, q = idx & 31;
        int gm = bm + m;
        float4 v = (gm < M) ? ((const float4*)(A + (size_t)gm * 128))[q]
                            : make_float4(0.f, 0.f, 0.f, 0.f);
        __half2 h0 = __floats2half2_rn(v.x, v.y);
        __half2 h1 = __floats2half2_rn(v.z, v.w);
        *(__half2*)&As[m * AS_STRIDE + q * 4]     = h0;
        *(__half2*)&As[m * AS_STRIDE + q * 4 + 2] = h1;
    }
    for (int idx = tid; idx < 2048; idx += 512) {
        int n = idx >> 4, q = idx & 15;
        *(uint4*)&Bs[n * AS_STRIDE + q * 8] = ((const uint4*)(g_w1t + n * 128))[q];
    }
    __syncthreads();

    int lane = tid & 31, warp = tid >> 5;
    int wm = (warp >> 2) * 32;
    int wn = (warp & 3) * 32;
    float acc[2][4][4];
#pragma unroll
    for (int i = 0; i < 2; i++)
#pragma unroll
        for (int j = 0; j < 4; j++)
#pragma unroll
            for (int r = 0; r < 4; r++) acc[i][j][r] = 0.f;

    int lr = (lane & 7) + ((lane >> 3) & 1) * 8;
    int lk = ((lane >> 4) & 1) * 8;
    int l16 = lane & 15;
    int brow = l16 & 7;
    int bk = ((l16 >> 3) & 1) * 8;

#pragma unroll
    for (int k0 = 0; k0 < 128; k0 += 16) {
        unsigned a[2][4];
#pragma unroll
        for (int fi = 0; fi < 2; fi++) {
            unsigned addr = smem_u32(&As[(wm + fi * 16 + lr) * AS_STRIDE + k0 + lk]);
            asm volatile("ldmatrix.sync.aligned.m8n8.x4.shared.b16 {%0,%1,%2,%3}, [%4];"
                         : "=r"(a[fi][0]), "=r"(a[fi][1]), "=r"(a[fi][2]), "=r"(a[fi][3])
                         : "r"(addr));
        }
        unsigned b[4][2];
#pragma unroll
        for (int fj = 0; fj < 4; fj++) {
            unsigned addr = smem_u32(&Bs[(wn + fj * 8 + brow) * AS_STRIDE + k0 + bk]);
            asm volatile("ldmatrix.sync.aligned.m8n8.x2.shared.b16 {%0,%1}, [%2];"
                         : "=r"(b[fj][0]), "=r"(b[fj][1])
                         : "r"(addr));
        }
#pragma unroll
        for (int fi = 0; fi < 2; fi++)
#pragma unroll
            for (int fj = 0; fj < 4; fj++) {
                asm volatile(
                    "mma.sync.aligned.m16n8k16.row.col.f32.f16.f16.f32 "
                    "{%0,%1,%2,%3}, {%4,%5,%6,%7}, {%8,%9}, {%0,%1,%2,%3};"
                    : "+f"(acc[fi][fj][0]), "+f"(acc[fi][fj][1]),
                      "+f"(acc[fi][fj][2]), "+f"(acc[fi][fj][3])
                    : "r"(a[fi][0]), "r"(a[fi][1]), "r"(a[fi][2]), "r"(a[fi][3]),
                      "r"(b[fj][0]), "r"(b[fj][1]));
            }
    }

    // epilogue: scale by dinv[row], convert to fp16, store pairs
#pragma unroll
    for (int fi = 0; fi < 2; fi++) {
        int r0 = bm + wm + fi * 16 + (lane >> 2);
        int r1 = r0 + 8;
        float d0 = (r0 < M) ? g_dinv[r0] : 0.f;
        float d1 = (r1 < M) ? g_dinv[r1] : 0.f;
#pragma unroll
        for (int fj = 0; fj < 4; fj++) {
            int c = wn + fj * 8 + (lane & 3) * 2;
            if (r0 < M)
                *(__half2*)(C + (size_t)r0 * 128 + c) =
                    __floats2half2_rn(acc[fi][fj][0] * d0, acc[fi][fj][1] * d0);
            if (r1 < M)
                *(__half2*)(C + (size_t)r1 * 128 + c) =
                    __floats2half2_rn(acc[fi][fj][2] * d1, acc[fi][fj][3] * d1);
        }
    }
}

// ---------------- layer-1 gather (R12 shape, unroll-4 for MLP) ----------------
// h1s[n] = fp16(dinv[n]*relu(dinv[n]*(sum xw1s[s] + xw1s[n]) + b1))
__global__ void gather1_kernel(const float* __restrict__ b1) {
    int n = (blockIdx.x * blockDim.x + threadIdx.x) >> 5;
    if (n >= NN) return;
    int lane = threadIdx.x & 31;       // lane covers features [lane*4, lane*4+4)
    int e = g_rowptr[n];
    int end = g_rowptr[n + 1];
    float4 acc = make_float4(0.f, 0.f, 0.f, 0.f);
    for (; e + 3 < end; e += 4) {
        int s0 = g_csr_src[e];
        int s1 = g_csr_src[e + 1];
        int s2 = g_csr_src[e + 2];
        int s3 = g_csr_src[e + 3];
        uint2 u0 = ((const uint2*)(g_xw1s + (size_t)s0 * F_H1))[lane];
        uint2 u1 = ((const uint2*)(g_xw1s + (size_t)s1 * F_H1))[lane];
        uint2 u2 = ((const uint2*)(g_xw1s + (size_t)s2 * F_H1))[lane];
        uint2 u3 = ((const uint2*)(g_xw1s + (size_t)s3 * F_H1))[lane];
        float2 p;
        p = __half22float2(*(__half2*)&u0.x); acc.x += p.x; acc.y += p.y;
        p = __half22float2(*(__half2*)&u0.y); acc.z += p.x; acc.w += p.y;
        p = __half22float2(*(__half2*)&u1.x); acc.x += p.x; acc.y += p.y;
        p = __half22float2(*(__half2*)&u1.y); acc.z += p.x; acc.w += p.y;
        p = __half22float2(*(__half2*)&u2.x); acc.x += p.x; acc.y += p.y;
        p = __half22float2(*(__half2*)&u2.y); acc.z += p.x; acc.w += p.y;
        p = __half22float2(*(__half2*)&u3.x); acc.x += p.x; acc.y += p.y;
        p = __half22float2(*(__half2*)&u3.y); acc.z += p.x; acc.w += p.y;
    }
    for (; e < end; e++) {
        int s0 = g_csr_src[e];
        uint2 u0 = ((const uint2*)(g_xw1s + (size_t)s0 * F_H1))[lane];
        float2 p;
        p = __half22float2(*(__half2*)&u0.x); acc.x += p.x; acc.y += p.y;
        p = __half22float2(*(__half2*)&u0.y); acc.z += p.x; acc.w += p.y;
    }
    float d = g_dinv[n];
    uint2 us = ((const uint2*)(g_xw1s + (size_t)n * F_H1))[lane];
    float2 sa = __half22float2(*(__half2*)&us.x), sb = __half22float2(*(__half2*)&us.y);
    float4 bb = ((const float4*)b1)[lane];
    float ox = d * fmaxf(fmaf(acc.x + sa.x, d, bb.x), 0.f);
    float oy = d * fmaxf(fmaf(acc.y + sa.y, d, bb.y), 0.f);
    float oz = d * fmaxf(fmaf(acc.z + sb.x, d, bb.z), 0.f);
    float ow = d * fmaxf(fmaf(acc.w + sb.y, d, bb.w), 0.f);
    __half2 h0 = __floats2half2_rn(ox, oy);
    __half2 h1 = __floats2half2_rn(oz, ow);
    uint2 o;
    o.x = *(unsigned*)&h0;
    o.y = *(unsigned*)&h1;
    ((uint2*)(g_h1s + (size_t)n * F_H1))[lane] = o;
}

// ---------------- layer-2 gather + fused pooling (R12 shape, unroll-4) ----------------
__global__ void gather2_pool_kernel(const int* __restrict__ batch) {
    int n = (blockIdx.x * blockDim.x + threadIdx.x) >> 5;
    if (n >= NN) return;
    int lane = threadIdx.x & 31;
    int e = g_rowptr[n];
    int end = g_rowptr[n + 1];
    float4 acc = make_float4(0.f, 0.f, 0.f, 0.f);
    for (; e + 3 < end; e += 4) {
        int s0 = g_csr_src[e];
        int s1 = g_csr_src[e + 1];
        int s2 = g_csr_src[e + 2];
        int s3 = g_csr_src[e + 3];
        uint2 u0 = ((const uint2*)(g_h1s + (size_t)s0 * F_H1))[lane];
        uint2 u1 = ((const uint2*)(g_h1s + (size_t)s1 * F_H1))[lane];
        uint2 u2 = ((const uint2*)(g_h1s + (size_t)s2 * F_H1))[lane];
        uint2 u3 = ((const uint2*)(g_h1s + (size_t)s3 * F_H1))[lane];
        float2 p;
        p = __half22float2(*(__half2*)&u0.x); acc.x += p.x; acc.y += p.y;
        p = __half22float2(*(__half2*)&u0.y); acc.z += p.x; acc.w += p.y;
        p = __half22float2(*(__half2*)&u1.x); acc.x += p.x; acc.y += p.y;
        p = __half22float2(*(__half2*)&u1.y); acc.z += p.x; acc.w += p.y;
        p = __half22float2(*(__half2*)&u2.x); acc.x += p.x; acc.y += p.y;
        p = __half22float2(*(__half2*)&u2.y); acc.z += p.x; acc.w += p.y;
        p = __half22float2(*(__half2*)&u3.x); acc.x += p.x; acc.y += p.y;
        p = __half22float2(*(__half2*)&u3.y); acc.z += p.x; acc.w += p.y;
    }
    for (; e < end; e++) {
        int s0 = g_csr_src[e];
        uint2 u0 = ((const uint2*)(g_h1s + (size_t)s0 * F_H1))[lane];
        float2 p;
        p = __half22float2(*(__half2*)&u0.x); acc.x += p.x; acc.y += p.y;
        p = __half22float2(*(__half2*)&u0.y); acc.z += p.x; acc.w += p.y;
    }
    float d = g_dinv[n];
    uint2 us = ((const uint2*)(g_h1s + (size_t)n * F_H1))[lane];
    float2 sa = __half22float2(*(__half2*)&us.x), sb = __half22float2(*(__half2*)&us.y);
    acc.x = (acc.x + sa.x) * d;
    acc.y = (acc.y + sa.y) * d;
    acc.z = (acc.z + sb.x) * d;
    acc.w = (acc.w + sb.y) * d;

    int g = batch[n];
    float* p = g_pool + (size_t)g * F_H1 + lane * 4;
    atomicAdd(p + 0, acc.x);
    atomicAdd(p + 1, acc.y);
    atomicAdd(p + 2, acc.z);
    atomicAdd(p + 3, acc.w);
    if (lane == 0) atomicAdd(&g_cnt[g], 1.0f);
}

// ---------------- heads: tiny @W2+b2 per graph, then group + family logits ----------------
__global__ void logits_kernel(const float* __restrict__ W2, const float* __restrict__ b2,
                              const float* __restrict__ Wg, const float* __restrict__ bg,
                              const float* __restrict__ Wf, const float* __restrict__ bf,
                              float* __restrict__ out) {
    __shared__ float p[F_H1];    // pooled mean, [128]
    __shared__ float h2[F_H2];   // pooled @ W2 + b2, [256]
    int b = blockIdx.x;          // graph
    int t = threadIdx.x;         // 256 threads
    float cnt = fmaxf(g_cnt[b], 1.0f);
    if (t < F_H1) p[t] = g_pool[b * F_H1 + t] / cnt;
    __syncthreads();

    {
        float s = b2[t];
#pragma unroll 8
        for (int k = 0; k < F_H1; k++) s = fmaf(p[k], W2[k * F_H2 + t], s);
        h2[t] = s;
    }
    __syncthreads();

    if (t < N_GROUPS) {
        float s = bg[t];
#pragma unroll 8
        for (int k = 0; k < F_H2; k++) s = fmaf(h2[k], Wg[k * N_GROUPS + t], s);
        out[b * N_GROUPS + t] = s;
    }
    if (t < N_GROUPS * N_FAM) {
        int g = t / N_FAM, f = t - g * N_FAM;
        float s = bf[g * N_FAM + f];
        const float* w = Wf + (size_t)g * F_H2 * N_FAM + f;
#pragma unroll 8
        for (int k = 0; k < F_H2; k++) s = fmaf(h2[k], w[k * N_FAM], s);
        out[NG * N_GROUPS + (size_t)g * NG * N_FAM + b * N_FAM + f] = s;
    }
}

// ---------------- launcher: dinv-gated stream overlap (R14 structure) ----------------
extern "C" void kernel_launch(void* const* d_in, const int* in_sizes, int n_in,
                              void* d_out, int out_size) {
    const float* x     = (const float*)d_in[0];
    const int*   ei    = (const int*)d_in[1];     // [2, NE] int32
    const int*   batch = (const int*)d_in[2];
    const float* W1    = (const float*)d_in[3];
    const float* b1    = (const float*)d_in[4];
    const float* W2    = (const float*)d_in[5];
    const float* b2    = (const float*)d_in[6];
    const float* Wg    = (const float*)d_in[7];
    const float* bg    = (const float*)d_in[8];
    const float* Wf    = (const float*)d_in[9];
    const float* bf    = (const float*)d_in[10];
    float* out = (float*)d_out;

    const int* src = ei;
    const int* dst = ei + NE;

    __half* xw1s;
    cudaGetSymbolAddress((void**)&xw1s, g_xw1s);

    const int GEMM_SMEM = 2 * 128 * AS_STRIDE * 2;   // 69632 B
    cudaFuncSetAttribute(gemm1_mma_kernel, cudaFuncAttributeMaxDynamicSharedMemorySize,
                         GEMM_SMEM);

    cudaStream_t s2;
    cudaStreamCreateWithFlags(&s2, cudaStreamNonBlocking);
    cudaEvent_t evFork, evDinv, evGemm;
    cudaEventCreateWithFlags(&evFork, cudaEventDisableTiming);
    cudaEventCreateWithFlags(&evDinv, cudaEventDisableTiming);
    cudaEventCreateWithFlags(&evGemm, cudaEventDisableTiming);

    // fork: w1t has no dependencies — runs immediately on s2
    cudaEventRecord(evFork, 0);
    cudaStreamWaitEvent(s2, evFork, 0);
    w1t_kernel<<<(F_H1 * F_IN + 255) / 256, 256, 0, s2>>>(W1);

    // main stream: histogram chain up to dinv availability
    zero_kernel<<<(NN + 255) / 256, 256>>>();
    hist_kernel<<<(NE + 255) / 256, 256>>>(dst);
    scan_block_kernel<<<NBLK_SCAN, SCAN_BLK>>>();      // produces dinv
    cudaEventRecord(evDinv, 0);

    // s2: gemm1 (needs dinv for its prescale epilogue) overlaps rest of CSR chain
    cudaStreamWaitEvent(s2, evDinv, 0);
    gemm1_mma_kernel<<<(NN + 127) / 128, 512, GEMM_SMEM, s2>>>(x, xw1s, NN);
    cudaEventRecord(evGemm, s2);

    // main stream: finish CSR build concurrently with gemm1
    scan_sums_kernel<<<1, 512>>>();
    scan_add_kernel<<<(NN + 255) / 256, 256>>>();
    csr_fill_kernel<<<(NE + 255) / 256, 256>>>(src, dst);

    // join: gathers need CSR + xw1s
    cudaStreamWaitEvent(0, evGemm, 0);
    gather1_kernel<<<(NN * 32 + 255) / 256, 256>>>(b1);
    gather2_pool_kernel<<<(NN * 32 + 255) / 256, 256>>>(batch);

    // heads: per-graph @W2+b2 then logits
    logits_kernel<<<NG, F_H2>>>(W2, b2, Wg, bg, Wf, bf, out);

    cudaEventDestroy(evFork);
    cudaEventDestroy(evDinv);
    cudaEventDestroy(evGemm);
    cudaStreamDestroy(s2);
}

// round 17
// speedup vs baseline: 1.4336x; 1.2262x over previous
#include <cuda_runtime.h>
#include <cuda_fp16.h>

#define NN 100000
#define NE 1600000
#define NG 512
#define F_IN 128
#define F_H1 128
#define F_H2 256
#define N_GROUPS 16
#define N_FAM 10

#define SCAN_BLK 256
#define NBLK_SCAN ((NN + SCAN_BLK - 1) / SCAN_BLK)   // 391
#define POOL_SLOTS 8

// ---------------- scratch (device globals: allocation-guard-safe) ----------------
__device__ __half g_xw1s[(size_t)NN * F_H1]; // dinv * (x @ W1), fp16 (25.6 MB, L2-resident)
__device__ __half g_h1s[(size_t)NN * F_H1];  // dinv * relu(agg1), fp16 (25.6 MB, L2-resident)
__device__ __half g_w1t[F_H1 * F_IN];        // W1 transposed [n][k], fp16
__device__ float g_dinv[NN];                 // rsqrt(deg+1)
__device__ int   g_deg[NN];                  // in-degree histogram
__device__ int   g_rowptr[NN + 1];           // CSR row pointers (by dst)
__device__ int   g_fill[NN];                 // running fill cursors
__device__ int   g_blocksum[NBLK_SCAN + 1];  // scan partials
__device__ int   g_csr_src[NE];              // src ids, dst-ordered
__device__ float g_pool[NG * F_H1];          // pooled sums [512,128] (fp32)
__device__ float g_cnt[NG];                  // segment counts

__device__ __forceinline__ unsigned smem_u32(const void* p) {
    unsigned a;
    asm("{.reg .u64 t; cvta.to.shared.u64 t, %1; cvt.u32.u64 %0, t;}" : "=r"(a) : "l"(p));
    return a;
}

// ---------------- zero + degree histogram ----------------
// NOTE: must cover NN threads (g_deg) — replay idempotence.
__global__ void zero_kernel() {
    int i = blockIdx.x * blockDim.x + threadIdx.x;
    if (i < NN) g_deg[i] = 0;
    if (i < NG * F_H1) g_pool[i] = 0.f;
    if (i < NG) g_cnt[i] = 0.f;
}

__global__ void hist_kernel(const int* __restrict__ dst) {
    int e = blockIdx.x * blockDim.x + threadIdx.x;
    if (e < NE) atomicAdd(&g_deg[dst[e]], 1);
}

// ---------------- exclusive scan of g_deg -> g_rowptr (dinv fused in) ----------------
__global__ void scan_block_kernel() {
    __shared__ int s[SCAN_BLK];
    int tid = threadIdx.x;
    int i = blockIdx.x * SCAN_BLK + tid;
    int v = (i < NN) ? g_deg[i] : 0;
    if (i < NN) g_dinv[i] = rsqrtf((float)v + 1.0f);   // fused dinv
    s[tid] = v;
    __syncthreads();
#pragma unroll
    for (int off = 1; off < SCAN_BLK; off <<= 1) {
        int t = (tid >= off) ? s[tid - off] : 0;
        __syncthreads();
        s[tid] += t;
        __syncthreads();
    }
    if (i < NN) g_rowptr[i] = s[tid] - v;      // exclusive within block
    if (tid == SCAN_BLK - 1) g_blocksum[blockIdx.x] = s[tid];
}

__global__ void scan_sums_kernel() {
    __shared__ int s[512];
    int tid = threadIdx.x;                      // 512 threads
    int v = (tid < NBLK_SCAN) ? g_blocksum[tid] : 0;
    s[tid] = v;
    __syncthreads();
#pragma unroll
    for (int off = 1; off < 512; off <<= 1) {
        int t = (tid >= off) ? s[tid - off] : 0;
        __syncthreads();
        s[tid] += t;
        __syncthreads();
    }
    if (tid < NBLK_SCAN) g_blocksum[tid] = s[tid] - v;   // exclusive
}

__global__ void scan_add_kernel() {
    int i = blockIdx.x * blockDim.x + threadIdx.x;
    if (i < NN) {
        int r = g_rowptr[i] + g_blocksum[i / SCAN_BLK];
        g_rowptr[i] = r;
        g_fill[i] = r;
    }
    if (i == 0) g_rowptr[NN] = NE;
}

// ---------------- CSR fill (src ids only) ----------------
__global__ void csr_fill_kernel(const int* __restrict__ src, const int* __restrict__ dst) {
    int e = blockIdx.x * blockDim.x + threadIdx.x;
    if (e >= NE) return;
    int pos = atomicAdd(&g_fill[dst[e]], 1);
    g_csr_src[pos] = src[e];
}

// ---------------- W1 transpose + fp16 convert: W1T[n][k] = W1[k][n] ----------------
__global__ void w1t_kernel(const float* __restrict__ W1) {
    int i = blockIdx.x * blockDim.x + threadIdx.x;   // 16384
    int n = i >> 7, k = i & 127;
    g_w1t[n * 128 + k] = __float2half(W1[k * 128 + n]);
}

// ---------------- GEMM1 (tensor cores): xw1s = fp16(dinv * (x @ W1)) ----------------
#define AS_STRIDE 136   // halves; 272B row stride -> conflict-free ldmatrix
__global__ __launch_bounds__(512) void gemm1_mma_kernel(const float* __restrict__ A,
                                                        __half* __restrict__ C, int M) {
    extern __shared__ char smem_raw[];
    __half* As = (__half*)smem_raw;                      // [128][AS_STRIDE]
    __half* Bs = As + 128 * AS_STRIDE;                   // [128][AS_STRIDE] (n-major)
    int tid = threadIdx.x;
    int bm = blockIdx.x * 128;

    for (int idx = tid; idx < 128 * 32; idx += 512) {
        int m = idx >> 5, q = idx & 31;
        int gm = bm + m;
        float4 v = (gm < M) ? ((const float4*)(A + (size_t)gm * 128))[q]
                            : make_float4(0.f, 0.f, 0.f, 0.f);
        __half2 h0 = __floats2half2_rn(v.x, v.y);
        __half2 h1 = __floats2half2_rn(v.z, v.w);
        *(__half2*)&As[m * AS_STRIDE + q * 4]     = h0;
        *(__half2*)&As[m * AS_STRIDE + q * 4 + 2] = h1;
    }
    for (int idx = tid; idx < 2048; idx += 512) {
        int n = idx >> 4, q = idx & 15;
        *(uint4*)&Bs[n * AS_STRIDE + q * 8] = ((const uint4*)(g_w1t + n * 128))[q];
    }
    __syncthreads();

    int lane = tid & 31, warp = tid >> 5;
    int wm = (warp >> 2) * 32;
    int wn = (warp & 3) * 32;
    float acc[2][4][4];
#pragma unroll
    for (int i = 0; i < 2; i++)
#pragma unroll
        for (int j = 0; j < 4; j++)
#pragma unroll
            for (int r = 0; r < 4; r++) acc[i][j][r] = 0.f;

    int lr = (lane & 7) + ((lane >> 3) & 1) * 8;
    int lk = ((lane >> 4) & 1) * 8;
    int l16 = lane & 15;
    int brow = l16 & 7;
    int bk = ((l16 >> 3) & 1) * 8;

#pragma unroll
    for (int k0 = 0; k0 < 128; k0 += 16) {
        unsigned a[2][4];
#pragma unroll
        for (int fi = 0; fi < 2; fi++) {
            unsigned addr = smem_u32(&As[(wm + fi * 16 + lr) * AS_STRIDE + k0 + lk]);
            asm volatile("ldmatrix.sync.aligned.m8n8.x4.shared.b16 {%0,%1,%2,%3}, [%4];"
                         : "=r"(a[fi][0]), "=r"(a[fi][1]), "=r"(a[fi][2]), "=r"(a[fi][3])
                         : "r"(addr));
        }
        unsigned b[4][2];
#pragma unroll
        for (int fj = 0; fj < 4; fj++) {
            unsigned addr = smem_u32(&Bs[(wn + fj * 8 + brow) * AS_STRIDE + k0 + bk]);
            asm volatile("ldmatrix.sync.aligned.m8n8.x2.shared.b16 {%0,%1}, [%2];"
                         : "=r"(b[fj][0]), "=r"(b[fj][1])
                         : "r"(addr));
        }
#pragma unroll
        for (int fi = 0; fi < 2; fi++)
#pragma unroll
            for (int fj = 0; fj < 4; fj++) {
                asm volatile(
                    "mma.sync.aligned.m16n8k16.row.col.f32.f16.f16.f32 "
                    "{%0,%1,%2,%3}, {%4,%5,%6,%7}, {%8,%9}, {%0,%1,%2,%3};"
                    : "+f"(acc[fi][fj][0]), "+f"(acc[fi][fj][1]),
                      "+f"(acc[fi][fj][2]), "+f"(acc[fi][fj][3])
                    : "r"(a[fi][0]), "r"(a[fi][1]), "r"(a[fi][2]), "r"(a[fi][3]),
                      "r"(b[fj][0]), "r"(b[fj][1]));
            }
    }

    // epilogue: scale by dinv[row], convert to fp16, store pairs
#pragma unroll
    for (int fi = 0; fi < 2; fi++) {
        int r0 = bm + wm + fi * 16 + (lane >> 2);
        int r1 = r0 + 8;
        float d0 = (r0 < M) ? g_dinv[r0] : 0.f;
        float d1 = (r1 < M) ? g_dinv[r1] : 0.f;
#pragma unroll
        for (int fj = 0; fj < 4; fj++) {
            int c = wn + fj * 8 + (lane & 3) * 2;
            if (r0 < M)
                *(__half2*)(C + (size_t)r0 * 128 + c) =
                    __floats2half2_rn(acc[fi][fj][0] * d0, acc[fi][fj][1] * d0);
            if (r1 < M)
                *(__half2*)(C + (size_t)r1 * 128 + c) =
                    __floats2half2_rn(acc[fi][fj][2] * d1, acc[fi][fj][3] * d1);
        }
    }
}

// ---------------- layer-1 gather (R14 proven shape: warp/node, uint2, unroll-2) ----------------
// h1s[n] = fp16(dinv[n]*relu(dinv[n]*(sum xw1s[s] + xw1s[n]) + b1))
__global__ void gather1_kernel(const float* __restrict__ b1) {
    int n = (blockIdx.x * blockDim.x + threadIdx.x) >> 5;
    if (n >= NN) return;
    int lane = threadIdx.x & 31;       // lane covers features [lane*4, lane*4+4)
    int e = g_rowptr[n];
    int end = g_rowptr[n + 1];
    float4 acc = make_float4(0.f, 0.f, 0.f, 0.f);
    for (; e + 1 < end; e += 2) {
        int s0 = g_csr_src[e];
        int s1 = g_csr_src[e + 1];
        uint2 u0 = ((const uint2*)(g_xw1s + (size_t)s0 * F_H1))[lane];
        uint2 u1 = ((const uint2*)(g_xw1s + (size_t)s1 * F_H1))[lane];
        float2 a0 = __half22float2(*(__half2*)&u0.x), b0 = __half22float2(*(__half2*)&u0.y);
        float2 a1 = __half22float2(*(__half2*)&u1.x), b1f = __half22float2(*(__half2*)&u1.y);
        acc.x += a0.x + a1.x;
        acc.y += a0.y + a1.y;
        acc.z += b0.x + b1f.x;
        acc.w += b0.y + b1f.y;
    }
    if (e < end) {
        int s0 = g_csr_src[e];
        uint2 u0 = ((const uint2*)(g_xw1s + (size_t)s0 * F_H1))[lane];
        float2 a0 = __half22float2(*(__half2*)&u0.x), b0 = __half22float2(*(__half2*)&u0.y);
        acc.x += a0.x; acc.y += a0.y; acc.z += b0.x; acc.w += b0.y;
    }
    float d = g_dinv[n];
    uint2 us = ((const uint2*)(g_xw1s + (size_t)n * F_H1))[lane];
    float2 sa = __half22float2(*(__half2*)&us.x), sb = __half22float2(*(__half2*)&us.y);
    float4 bb = ((const float4*)b1)[lane];
    float ox = d * fmaxf(fmaf(acc.x + sa.x, d, bb.x), 0.f);
    float oy = d * fmaxf(fmaf(acc.y + sa.y, d, bb.y), 0.f);
    float oz = d * fmaxf(fmaf(acc.z + sb.x, d, bb.z), 0.f);
    float ow = d * fmaxf(fmaf(acc.w + sb.y, d, bb.w), 0.f);
    __half2 h0 = __floats2half2_rn(ox, oy);
    __half2 h1 = __floats2half2_rn(oz, ow);
    uint2 o;
    o.x = *(unsigned*)&h0;
    o.y = *(unsigned*)&h1;
    ((uint2*)(g_h1s + (size_t)n * F_H1))[lane] = o;
}

// ---------------- layer-2 gather + block-staged pooling ----------------
// Inner loop identical to R14. Epilogue: batch is SORTED, so the 8 consecutive
// nodes of a block span ~1 graph. Stage per-graph sums in smem (slot = g - g_first),
// then flush once per occupied slot — ~8x fewer global pool atomics.
__global__ __launch_bounds__(256) void gather2_pool_kernel(const int* __restrict__ batch) {
    __shared__ float spool[POOL_SLOTS][F_H1];
    __shared__ float scnt[POOL_SLOTS];
    __shared__ int sg_first;
    __shared__ int smaxslot;
    int tid = threadIdx.x;
    int warp = tid >> 5, lane = tid & 31;
    int nodes_base = blockIdx.x * 8;

    for (int i = tid; i < POOL_SLOTS * F_H1; i += 256)
        ((float*)spool)[i] = 0.f;
    if (tid < POOL_SLOTS) scnt[tid] = 0.f;
    if (tid == 0) {
        int nb = nodes_base < NN ? nodes_base : NN - 1;
        sg_first = batch[nb];
        smaxslot = 0;
    }
    __syncthreads();

    int n = nodes_base + warp;
    if (n < NN) {
        int e = g_rowptr[n];
        int end = g_rowptr[n + 1];
        float4 acc = make_float4(0.f, 0.f, 0.f, 0.f);
        for (; e + 1 < end; e += 2) {
            int s0 = g_csr_src[e];
            int s1 = g_csr_src[e + 1];
            uint2 u0 = ((const uint2*)(g_h1s + (size_t)s0 * F_H1))[lane];
            uint2 u1 = ((const uint2*)(g_h1s + (size_t)s1 * F_H1))[lane];
            float2 a0 = __half22float2(*(__half2*)&u0.x), b0 = __half22float2(*(__half2*)&u0.y);
            float2 a1 = __half22float2(*(__half2*)&u1.x), b1f = __half22float2(*(__half2*)&u1.y);
            acc.x += a0.x + a1.x;
            acc.y += a0.y + a1.y;
            acc.z += b0.x + b1f.x;
            acc.w += b0.y + b1f.y;
        }
        if (e < end) {
            int s0 = g_csr_src[e];
            uint2 u0 = ((const uint2*)(g_h1s + (size_t)s0 * F_H1))[lane];
            float2 a0 = __half22float2(*(__half2*)&u0.x), b0 = __half22float2(*(__half2*)&u0.y);
            acc.x += a0.x; acc.y += a0.y; acc.z += b0.x; acc.w += b0.y;
        }
        float d = g_dinv[n];
        uint2 us = ((const uint2*)(g_h1s + (size_t)n * F_H1))[lane];
        float2 sa = __half22float2(*(__half2*)&us.x), sb = __half22float2(*(__half2*)&us.y);
        acc.x = (acc.x + sa.x) * d;
        acc.y = (acc.y + sa.y) * d;
        acc.z = (acc.z + sb.x) * d;
        acc.w = (acc.w + sb.y) * d;

        int g = batch[n];
        int slot = g - sg_first;
        if (slot < POOL_SLOTS) {
            if (lane == 0) {
                atomicMax(&smaxslot, slot);
                atomicAdd(&scnt[slot], 1.0f);
            }
            float* sp = &spool[slot][lane * 4];
            atomicAdd(sp + 0, acc.x);
            atomicAdd(sp + 1, acc.y);
            atomicAdd(sp + 2, acc.z);
            atomicAdd(sp + 3, acc.w);
        } else {   // pathological block spanning >8 graphs: direct global fallback
            float* p = g_pool + (size_t)g * F_H1 + lane * 4;
            atomicAdd(p + 0, acc.x);
            atomicAdd(p + 1, acc.y);
            atomicAdd(p + 2, acc.z);
            atomicAdd(p + 3, acc.w);
            if (lane == 0) atomicAdd(&g_cnt[g], 1.0f);
        }
    }
    __syncthreads();

    int span = smaxslot + 1;
    for (int i = tid; i < span * F_H1; i += 256) {
        int s = i >> 7, f = i & 127;
        float v = spool[s][f];
        if (v != 0.f) atomicAdd(&g_pool[(size_t)(sg_first + s) * F_H1 + f], v);
    }
    if (tid < span) {
        float c = scnt[tid];
        if (c != 0.f) atomicAdd(&g_cnt[sg_first + tid], c);
    }
}

// ---------------- heads: tiny @W2+b2 per graph, then group + family logits ----------------
__global__ void logits_kernel(const float* __restrict__ W2, const float* __restrict__ b2,
                              const float* __restrict__ Wg, const float* __restrict__ bg,
                              const float* __restrict__ Wf, const float* __restrict__ bf,
                              float* __restrict__ out) {
    __shared__ float p[F_H1];    // pooled mean, [128]
    __shared__ float h2[F_H2];   // pooled @ W2 + b2, [256]
    int b = blockIdx.x;          // graph
    int t = threadIdx.x;         // 256 threads
    float cnt = fmaxf(g_cnt[b], 1.0f);
    if (t < F_H1) p[t] = g_pool[b * F_H1 + t] / cnt;
    __syncthreads();

    {
        float s = b2[t];
#pragma unroll 8
        for (int k = 0; k < F_H1; k++) s = fmaf(p[k], W2[k * F_H2 + t], s);
        h2[t] = s;
    }
    __syncthreads();

    if (t < N_GROUPS) {
        float s = bg[t];
#pragma unroll 8
        for (int k = 0; k < F_H2; k++) s = fmaf(h2[k], Wg[k * N_GROUPS + t], s);
        out[b * N_GROUPS + t] = s;
    }
    if (t < N_GROUPS * N_FAM) {
        int g = t / N_FAM, f = t - g * N_FAM;
        float s = bf[g * N_FAM + f];
        const float* w = Wf + (size_t)g * F_H2 * N_FAM + f;
#pragma unroll 8
        for (int k = 0; k < F_H2; k++) s = fmaf(h2[k], w[k * N_FAM], s);
        out[NG * N_GROUPS + (size_t)g * NG * N_FAM + b * N_FAM + f] = s;
    }
}

// ---------------- launcher: dinv-gated stream overlap (R14 structure) ----------------
extern "C" void kernel_launch(void* const* d_in, const int* in_sizes, int n_in,
                              void* d_out, int out_size) {
    const float* x     = (const float*)d_in[0];
    const int*   ei    = (const int*)d_in[1];     // [2, NE] int32
    const int*   batch = (const int*)d_in[2];
    const float* W1    = (const float*)d_in[3];
    const float* b1    = (const float*)d_in[4];
    const float* W2    = (const float*)d_in[5];
    const float* b2    = (const float*)d_in[6];
    const float* Wg    = (const float*)d_in[7];
    const float* bg    = (const float*)d_in[8];
    const float* Wf    = (const float*)d_in[9];
    const float* bf    = (const float*)d_in[10];
    float* out = (float*)d_out;

    const int* src = ei;
    const int* dst = ei + NE;

    __half* xw1s;
    cudaGetSymbolAddress((void**)&xw1s, g_xw1s);

    const int GEMM_SMEM = 2 * 128 * AS_STRIDE * 2;   // 69632 B
    cudaFuncSetAttribute(gemm1_mma_kernel, cudaFuncAttributeMaxDynamicSharedMemorySize,
                         GEMM_SMEM);

    cudaStream_t s2;
    cudaStreamCreateWithFlags(&s2, cudaStreamNonBlocking);
    cudaEvent_t evFork, evDinv, evGemm;
    cudaEventCreateWithFlags(&evFork, cudaEventDisableTiming);
    cudaEventCreateWithFlags(&evDinv, cudaEventDisableTiming);
    cudaEventCreateWithFlags(&evGemm, cudaEventDisableTiming);

    // fork: w1t has no dependencies — runs immediately on s2
    cudaEventRecord(evFork, 0);
    cudaStreamWaitEvent(s2, evFork, 0);
    w1t_kernel<<<(F_H1 * F_IN + 255) / 256, 256, 0, s2>>>(W1);

    // main stream: histogram chain up to dinv availability
    zero_kernel<<<(NN + 255) / 256, 256>>>();
    hist_kernel<<<(NE + 255) / 256, 256>>>(dst);
    scan_block_kernel<<<NBLK_SCAN, SCAN_BLK>>>();      // produces dinv
    cudaEventRecord(evDinv, 0);

    // s2: gemm1 (needs dinv for its prescale epilogue) overlaps rest of CSR chain
    cudaStreamWaitEvent(s2, evDinv, 0);
    gemm1_mma_kernel<<<(NN + 127) / 128, 512, GEMM_SMEM, s2>>>(x, xw1s, NN);
    cudaEventRecord(evGemm, s2);

    // main stream: finish CSR build concurrently with gemm1
    scan_sums_kernel<<<1, 512>>>();
    scan_add_kernel<<<(NN + 255) / 256, 256>>>();
    csr_fill_kernel<<<(NE + 255) / 256, 256>>>(src, dst);

    // join: gathers need CSR + xw1s
    cudaStreamWaitEvent(0, evGemm, 0);
    gather1_kernel<<<(NN * 32 + 255) / 256, 256>>>(b1);
    gather2_pool_kernel<<<NN / 8, 256>>>(batch);

    // heads: per-graph @W2+b2 then logits
    logits_kernel<<<NG, F_H2>>>(W2, b2, Wg, bg, Wf, bf, out);

    cudaEventDestroy(evFork);
    cudaEventDestroy(evDinv);
    cudaEventDestroy(evGemm);
    cudaStreamDestroy(s2);
}